// round 16
// baseline (speedup 1.0000x reference)
#include <cuda_runtime.h>
#include <cuda_bf16.h>
#include <math.h>
#include <stdint.h>

// Problem constants
#define B_   1024
#define T_   64
#define H_   512
#define V_   1024
#define G_   100
#define FH_  2048   // 4*H

// GEMM tiling: CTA tile 64(M) x 128(N'), BK=32, 8 GEMM warps (32x32 each), 2 CTAs/SM
#define MT_   16
#define NT_   16
#define GRID_ 256
#define BK_   32
#define NK_   16
#define APL_  4096    // A plane bytes: 64 rows * 64B
#define BPL_  8192    // B plane bytes: 128 rows * 64B
#define STAGE_B 36864 // 3*APL + 3*BPL
#define NSTG  2
#define HR    4       // head rows per CTA
#define HEAD_OFF (NSTG * STAGE_B)                               // 73728
#define SMEM_TOT (HEAD_OFF + HR * V_ * 4 + HR * (G_ + 4) * 4)  // 91776 -> 2 CTAs/SM

// ---------------- persistent device scratch ----------------
__device__ float g_h[2][B_ * H_];
__device__ float g_c[B_ * H_];
__device__ int   g_tok[B_];
__device__ float g_bR[FH_];
__device__ float g_WihR[(size_t)V_ * FH_];
__device__ __nv_bfloat16 g_Bs[3][(size_t)FH_ * H_];
__device__ __nv_bfloat16 g_Ab[2][3][B_][H_];
__device__ float g_W1T[H_ * G_];
__device__ float g_W2T[G_ * V_];
__device__ unsigned g_edc[GRID_];  // per-CTA epilogue-done (A-chunk producer) flags
__device__ unsigned g_ed[16];      // per-m-group epilogue-done counters (head waits)
__device__ unsigned g_hd[16];      // per-m-group head-done (tok ready) counters

__device__ __forceinline__ int np_to_gr(int np) {
    int nt = np >> 7, rem = np & 127, jl = rem >> 2, gg = rem & 3;
    return gg * 512 + nt * 32 + jl;
}

__device__ __forceinline__ uint32_t smem_u32(const void* p) {
    uint32_t a;
    asm("{ .reg .u64 t; cvta.to.shared.u64 t, %1; cvt.u32.u64 %0, t; }" : "=r"(a) : "l"(p));
    return a;
}

#define CP16(dst, src) \
    asm volatile("cp.async.cg.shared.global [%0], [%1], 16;" :: "r"(dst), "l"(src) : "memory")
#define CP_WAIT_ALL() asm volatile("cp.async.wait_all;" ::: "memory")

#define LDM_X4(r0, r1, r2, r3, addr) \
    asm volatile("ldmatrix.sync.aligned.m8n8.x4.shared.b16 {%0,%1,%2,%3}, [%4];" \
                 : "=r"(r0), "=r"(r1), "=r"(r2), "=r"(r3) : "r"(addr))

#define MMA16816(d0, d1, d2, d3, a0, a1, a2, a3, b0, b1) \
    asm volatile("mma.sync.aligned.m16n8k16.row.col.f32.bf16.bf16.f32 " \
                 "{%0,%1,%2,%3}, {%4,%5,%6,%7}, {%8,%9}, {%0,%1,%2,%3};" \
                 : "+f"(d0), "+f"(d1), "+f"(d2), "+f"(d3) \
                 : "r"(a0), "r"(a1), "r"(a2), "r"(a3), "r"(b0), "r"(b1))

#define BAR_GEMM() asm volatile("bar.sync 1, 256;" ::: "memory")   // warps 0-7
#define BAR_HEAD() asm volatile("bar.sync 2, 128;" ::: "memory")   // warps 8-11

__device__ __forceinline__ void split3(float v, __nv_bfloat16& s0, __nv_bfloat16& s1, __nv_bfloat16& s2) {
    s0 = __float2bfloat16_rn(v);
    float r1 = v - __bfloat162float(s0);
    s1 = __float2bfloat16_rn(r1);
    float r2 = r1 - __bfloat162float(s1);
    s2 = __float2bfloat16_rn(r2);
}

__device__ __forceinline__ uint32_t pl_off(int r, int q) {
    return (uint32_t)(r * 64 + ((q ^ ((r >> 1) & 3)) << 4));
}

__device__ __forceinline__ unsigned ld_flag(const unsigned* p) {
    unsigned v;
    asm volatile("ld.global.cg.u32 %0, [%1];" : "=r"(v) : "l"(p) : "memory");
    return v;
}

__device__ __forceinline__ void spin_ge(unsigned* cnt, unsigned tgt) {
    while (atomicAdd(cnt, 0u) < tgt) { }
    __threadfence();
}

// ---------------- init: h0/c0 (+bf16x3 planes), tok0, flag reset ----------------
__global__ void init_kernel(const float* __restrict__ inp,
                            const float* __restrict__ onehots,
                            const float* __restrict__ Wh, const float* __restrict__ bh,
                            const float* __restrict__ Wc, const float* __restrict__ bc) {
    int b = blockIdx.x;
    if (b == 0) {
        if (threadIdx.x < GRID_) g_edc[threadIdx.x] = 0u;
        if (threadIdx.x < 16) { g_ed[threadIdx.x] = 0u; g_hd[threadIdx.x] = 0u; }
    }
    float x = inp[b];
    for (int j = threadIdx.x; j < H_; j += blockDim.x) {
        float h0 = x * Wh[j] + bh[j];
        g_h[0][b * H_ + j] = h0;
        g_c[b * H_ + j]    = x * Wc[j] + bc[j];
        __nv_bfloat16 s0, s1, s2;
        split3(h0, s0, s1, s2);
        g_Ab[0][0][b][j] = s0;
        g_Ab[0][1][b][j] = s1;
        g_Ab[0][2][b][j] = s2;
    }
    const float* oh = onehots + (size_t)b * T_ * V_;
    for (int v = threadIdx.x; v < V_; v += blockDim.x)
        if (oh[v] > 0.5f) g_tok[b] = v;
}

// ---------------- prep: Whh -> 3 bf16 planes (reordered) + combined bias ----------------
__global__ void prep_B(const float* __restrict__ Whh,
                       const float* __restrict__ bih, const float* __restrict__ bhh) {
    int np = blockIdx.x;
    int gr = np_to_gr(np);
    if (threadIdx.x == 0) g_bR[np] = bih[gr] + bhh[gr];
    for (int k = threadIdx.x; k < H_; k += blockDim.x) {
        __nv_bfloat16 s0, s1, s2;
        split3(Whh[(size_t)gr * H_ + k], s0, s1, s2);
        size_t o = (size_t)np * H_ + k;
        g_Bs[0][o] = s0; g_Bs[1][o] = s1; g_Bs[2][o] = s2;
    }
}

// ---------------- prep: Wih reorder + head weight transposes ----------------
__global__ void prep_misc(const float* __restrict__ Wih,
                          const float* __restrict__ W1,
                          const float* __restrict__ W2) {
    int bid = blockIdx.x;
    if (bid < V_) {
        for (int np = threadIdx.x; np < FH_; np += blockDim.x) {
            int gr = np_to_gr(np);
            g_WihR[(size_t)bid * FH_ + np] = Wih[(size_t)gr * V_ + bid];
        }
    } else {
        int e = (bid - V_) * 256 + threadIdx.x;
        if (e < H_ * G_) {
            int k = e / G_, gg = e % G_;
            g_W1T[e] = W1[gg * H_ + k];
        } else if (e < H_ * G_ + G_ * V_) {
            int e2 = e - H_ * G_;
            int k = e2 / V_, v = e2 % V_;
            g_W2T[e2] = W2[v * G_ + k];
        }
    }
}

// ---------------- persistent fused kernel ----------------
// Distributed sync:
//   GEMM_t chunk kc waits g_edc[mt*16+kc] >= t  (A chunk kc of group mt is written
//     solely by CTA (mt, nt=kc)'s epilogue of step t-1)
//   head_{t-1} (bid) waits g_ed[bid>>4] >= 16t, then increments g_hd[bid>>4]
//   epi_t (mt,nt) waits g_hd[mt] >= 16t, then increments g_edc[mt*16+nt] and g_ed[mt]
__global__ __launch_bounds__(384, 2) void step_kernel(const float* __restrict__ b1,
                                                      const float* __restrict__ b2,
                                                      float* __restrict__ out) {
    extern __shared__ char smem[];
    const int tid = threadIdx.x, wid = tid >> 5, lane = tid & 31;
    const int mt = blockIdx.x, nt = blockIdx.y;
    const int bid = blockIdx.y * MT_ + blockIdx.x;     // 0..255
    const int row0 = bid * HR;                         // head rows
    const int hgrp = bid >> 4;                         // head's h/tok m-group
    uint32_t smem_base = smem_u32(smem);

    float* hbuf = (float*)(smem + HEAD_OFF);
    float (*sh_lg)[V_]     = (float (*)[V_])hbuf;
    float (*sh_h)[H_]      = (float (*)[H_])hbuf;      // alias: phase1 only
    float (*sh_r)[G_ + 4]  = (float (*)[G_ + 4])(hbuf + HR * V_);

    // GEMM-side lane constants (warps 0-7): 2x4 warp grid, warp tile 32m x 32n
    const int gq = lane >> 2, tq = lane & 3;
    const int mwarp = (wid >> 2) * 32;
    const int nwarp = (wid & 3) * 32;
    const int t8 = lane >> 3, lr = lane & 7;
    const int thi = t8 >> 1, tlo = t8 & 1;
    uint32_t aBase[2], aX[2];
    #pragma unroll
    for (int mi = 0; mi < 2; mi++) {
        int r = mwarp + mi * 16 + (tlo << 3) + lr;
        aBase[mi] = (uint32_t)(r * 64);
        aX[mi] = (uint32_t)(((r >> 1) & 3) << 4);
    }
    uint32_t bBase[2], bX[2];
    #pragma unroll
    for (int nih = 0; nih < 2; nih++) {
        int n = nwarp + nih * 16 + (thi << 3) + lr;
        bBase[nih] = (uint32_t)(n * 64);
        bX[nih] = (uint32_t)(((n >> 1) & 3) << 4);
    }
    const int ht = tid - 256;                          // head thread id (warps 8-11)

    // B half of a chunk (step-invariant; issued BEFORE the A-flag wait)
    #define LOAD_B(kc, st) do { \
        uint32_t bb = smem_base + (st) * STAGE_B + 3 * APL_; \
        _Pragma("unroll") \
        for (int s = 0; s < 6; s++) { \
            int e = tid + 256 * s; \
            int p = e >> 9, rem = e & 511, n = rem >> 2, q = rem & 3; \
            CP16(bb + p * BPL_ + pl_off(n, q), \
                 &g_Bs[p][(size_t)(nt * 128 + n) * H_ + (kc) * BK_ + q * 8]); \
        } \
    } while (0)

    // A half of a chunk (depends on epi_{t-1} of CTA (mt, kc))
    #define LOAD_A(kc, st, par) do { \
        uint32_t bb = smem_base + (st) * STAGE_B; \
        _Pragma("unroll") \
        for (int s = 0; s < 3; s++) { \
            int e = tid + 256 * s; \
            int p = e >> 8, rem = e & 255, n = rem >> 2, q = rem & 3; \
            CP16(bb + p * APL_ + pl_off(n, q), \
                 &g_Ab[par][p][mt * 64 + n][(kc) * BK_ + q * 8]); \
        } \
    } while (0)

    #define WAIT_A(kc, t) do { \
        const unsigned* f = &g_edc[mt * 16 + (kc)]; \
        while (ld_flag(f) < (unsigned)(t)) { } \
    } while (0)

    for (int t = 0; t <= T_; t++) {
        int par = t & 1;
        float acc[2][4][4];

        if (wid < 8) {
            if (t < T_) {
                // =========== gates GEMM for step t ===========
                #pragma unroll
                for (int mi = 0; mi < 2; mi++)
                    #pragma unroll
                    for (int n8 = 0; n8 < 4; n8++)
                        #pragma unroll
                        for (int q = 0; q < 4; q++) acc[mi][n8][q] = 0.0f;

                LOAD_B(0, 0);
                WAIT_A(0, t);
                LOAD_A(0, 0, par);
                CP_WAIT_ALL();
                BAR_GEMM();

                for (int kc = 0; kc < NK_; kc++) {
                    int cur = kc & 1, nxt = cur ^ 1;
                    if (kc + 1 < NK_) {
                        LOAD_B(kc + 1, nxt);
                        WAIT_A(kc + 1, t);
                        LOAD_A(kc + 1, nxt, par);
                    }
                    uint32_t sbase = smem_base + cur * STAGE_B;
                    #pragma unroll
                    for (int kk = 0; kk < 2; kk++) {
                        uint32_t aCh = (uint32_t)((kk * 2 + thi) << 4);
                        uint32_t bCh = (uint32_t)((kk * 2 + tlo) << 4);
                        uint32_t afr[3][2][4];
                        #pragma unroll
                        for (int pa = 0; pa < 3; pa++)
                            #pragma unroll
                            for (int mi = 0; mi < 2; mi++)
                                LDM_X4(afr[pa][mi][0], afr[pa][mi][1], afr[pa][mi][2], afr[pa][mi][3],
                                       sbase + pa * APL_ + aBase[mi] + (aCh ^ aX[mi]));
                        #pragma unroll
                        for (int pb = 0; pb < 3; pb++) {
                            uint32_t bfr[2][4];
                            #pragma unroll
                            for (int nih = 0; nih < 2; nih++)
                                LDM_X4(bfr[nih][0], bfr[nih][1], bfr[nih][2], bfr[nih][3],
                                       sbase + 3 * APL_ + pb * BPL_ + bBase[nih] + (bCh ^ bX[nih]));
                            #pragma unroll
                            for (int pa = 0; pa < 3; pa++) {
                                if (pa + pb > 2) break;
                                #pragma unroll
                                for (int mi = 0; mi < 2; mi++)
                                    #pragma unroll
                                    for (int n8 = 0; n8 < 4; n8++)
                                        MMA16816(acc[mi][n8][0], acc[mi][n8][1], acc[mi][n8][2], acc[mi][n8][3],
                                                 afr[pa][mi][0], afr[pa][mi][1], afr[pa][mi][2], afr[pa][mi][3],
                                                 bfr[n8 >> 1][(n8 & 1) * 2], bfr[n8 >> 1][(n8 & 1) * 2 + 1]);
                            }
                        }
                    }
                    CP_WAIT_ALL();
                    BAR_GEMM();
                }

                // =========== epilogue: wait tok_{t-1}, LSTM update, publish ===========
                if (tid == 0 && t > 0) spin_ge(&g_hd[mt], 16u * (unsigned)t);
                BAR_GEMM();

                float* __restrict__ hout = g_h[par ^ 1];
                #pragma unroll
                for (int mi = 0; mi < 2; mi++) {
                    int r0 = mwarp + mi * 16 + gq;
                    int m0 = mt * 64 + r0;
                    int m1 = m0 + 8;
                    int tok0 = __ldcg(&g_tok[m0]);
                    int tok1 = __ldcg(&g_tok[m1]);
                    const float* w0 = g_WihR + (size_t)tok0 * FH_;
                    const float* w1 = g_WihR + (size_t)tok1 * FH_;
                    #pragma unroll
                    for (int n8 = 0; n8 < 4; n8++) {
                        float c0 = acc[mi][n8][0], c1 = acc[mi][n8][1];
                        float c2 = acc[mi][n8][2], c3 = acc[mi][n8][3];
                        float gv0 = __shfl_xor_sync(0xffffffffu, c0, 1);
                        float ov0 = __shfl_xor_sync(0xffffffffu, c1, 1);
                        float gv1 = __shfl_xor_sync(0xffffffffu, c2, 1);
                        float ov1 = __shfl_xor_sync(0xffffffffu, c3, 1);
                        if (!(lane & 1)) {
                            int colq = nt * 128 + nwarp + n8 * 8 + 2 * tq;
                            float4 b4 = *(const float4*)&g_bR[colq];
                            float4 wa = *(const float4*)&w0[colq];
                            float4 wb = *(const float4*)&w1[colq];
                            int j = colq >> 2;
                            {
                                float gi = c0 + wa.x + b4.x;
                                float gf = c1 + wa.y + b4.y;
                                float gg = gv0 + wa.z + b4.z;
                                float go = ov0 + wa.w + b4.w;
                                float si = 1.0f / (1.0f + expf(-gi));
                                float sf = 1.0f / (1.0f + expf(-gf));
                                float so = 1.0f / (1.0f + expf(-go));
                                size_t idx = (size_t)m0 * H_ + j;
                                float cn = sf * g_c[idx] + si * tanhf(gg);
                                float hn = so * tanhf(cn);
                                g_c[idx] = cn;
                                hout[idx] = hn;
                                __nv_bfloat16 s0, s1, s2;
                                split3(hn, s0, s1, s2);
                                g_Ab[par ^ 1][0][m0][j] = s0;
                                g_Ab[par ^ 1][1][m0][j] = s1;
                                g_Ab[par ^ 1][2][m0][j] = s2;
                            }
                            {
                                float gi = c2 + wb.x + b4.x;
                                float gf = c3 + wb.y + b4.y;
                                float gg = gv1 + wb.z + b4.z;
                                float go = ov1 + wb.w + b4.w;
                                float si = 1.0f / (1.0f + expf(-gi));
                                float sf = 1.0f / (1.0f + expf(-gf));
                                float so = 1.0f / (1.0f + expf(-go));
                                size_t idx = (size_t)m1 * H_ + j;
                                float cn = sf * g_c[idx] + si * tanhf(gg);
                                float hn = so * tanhf(cn);
                                g_c[idx] = cn;
                                hout[idx] = hn;
                                __nv_bfloat16 s0, s1, s2;
                                split3(hn, s0, s1, s2);
                                g_Ab[par ^ 1][0][m1][j] = s0;
                                g_Ab[par ^ 1][1][m1][j] = s1;
                                g_Ab[par ^ 1][2][m1][j] = s2;
                            }
                        }
                    }
                }
                BAR_GEMM();
                if (tid == 0) {
                    __threadfence();
                    atomicAdd(&g_edc[mt * 16 + nt], 1u);
                    atomicAdd(&g_ed[mt], 1u);
                }
            }
        } else {
            // =========== head for step t-1 (concurrent with GEMM_t) ===========
            if (t >= 1) {
                if (ht == 0) spin_ge(&g_ed[hgrp], 16u * (unsigned)t);
                BAR_HEAD();

                const float* __restrict__ h = g_h[par];   // written by epi_{t-1}
                for (int e = ht; e < HR * H_ / 4; e += 128) {
                    int rr = e >> 7, q = e & 127;
                    float4 v = __ldcg((const float4*)&h[(size_t)(row0 + rr) * H_ + q * 4]);
                    *(float4*)&sh_h[rr][q * 4] = v;
                }
                BAR_HEAD();
                if (ht < G_) {
                    float a4[HR] = {0.f, 0.f, 0.f, 0.f};
                    for (int k = 0; k < H_; k++) {
                        float w = g_W1T[k * G_ + ht];
                        #pragma unroll
                        for (int r2 = 0; r2 < HR; r2++) a4[r2] += w * sh_h[r2][k];
                    }
                    float bb = b1[ht];
                    #pragma unroll
                    for (int r2 = 0; r2 < HR; r2++) sh_r[r2][ht] = fmaxf(a4[r2] + bb, 0.0f);
                }
                BAR_HEAD();
                #pragma unroll
                for (int s = 0; s < 8; s++) {
                    int v = ht + 128 * s;
                    float a4[HR];
                    #pragma unroll
                    for (int rr = 0; rr < HR; rr++) a4[rr] = 0.0f;
                    for (int k = 0; k < G_; k++) {
                        float w = g_W2T[k * V_ + v];
                        #pragma unroll
                        for (int rr = 0; rr < HR; rr++) a4[rr] += w * sh_r[rr][k];
                    }
                    float bb = b2[v];
                    #pragma unroll
                    for (int rr = 0; rr < HR; rr++) sh_lg[rr][v] = a4[rr] + bb;
                }
                BAR_HEAD();
                // softmax/argmax: 1 warp per row
                {
                    int rr = wid - 8;
                    float x[32];
                    #pragma unroll
                    for (int q = 0; q < 8; q++) {
                        float4 v4 = *(const float4*)&sh_lg[rr][q * 128 + lane * 4];
                        x[q * 4 + 0] = v4.x; x[q * 4 + 1] = v4.y; x[q * 4 + 2] = v4.z; x[q * 4 + 3] = v4.w;
                    }
                    float m = x[0];
                    int mi = lane * 4;
                    #pragma unroll
                    for (int q = 0; q < 8; q++)
                        #pragma unroll
                        for (int e = 0; e < 4; e++) {
                            if (q == 0 && e == 0) continue;
                            int col = q * 128 + lane * 4 + e;
                            float v = x[q * 4 + e];
                            if (v > m || (v == m && col < mi)) { m = v; mi = col; }
                        }
                    #pragma unroll
                    for (int o = 16; o > 0; o >>= 1) {
                        float om = __shfl_down_sync(0xffffffffu, m, o);
                        int oi = __shfl_down_sync(0xffffffffu, mi, o);
                        if (om > m || (om == m && oi < mi)) { m = om; mi = oi; }
                    }
                    float fm = __shfl_sync(0xffffffffu, m, 0);
                    int fi = __shfl_sync(0xffffffffu, mi, 0);
                    if (lane == 0) g_tok[row0 + rr] = fi;

                    float sum = 0.0f;
                    #pragma unroll
                    for (int e = 0; e < 32; e++) sum += __expf(x[e] - fm);
                    #pragma unroll
                    for (int o = 16; o > 0; o >>= 1) sum += __shfl_xor_sync(0xffffffffu, sum, o);
                    float lse = fm + __logf(sum);

                    float* orow = out + (size_t)(t - 1) * B_ * V_ + (size_t)(row0 + rr) * V_;
                    #pragma unroll
                    for (int q = 0; q < 8; q++) {
                        float4 ov = make_float4(x[q * 4 + 0] - lse, x[q * 4 + 1] - lse,
                                                x[q * 4 + 2] - lse, x[q * 4 + 3] - lse);
                        *(float4*)&orow[q * 128 + lane * 4] = ov;
                    }
                }
                BAR_HEAD();
                if (ht == 0) { __threadfence(); atomicAdd(&g_hd[hgrp], 1u); }
            }
        }
    }
    #undef LOAD_B
    #undef LOAD_A
    #undef WAIT_A
}

// ---------------- launch ----------------
extern "C" void kernel_launch(void* const* d_in, const int* in_sizes, int n_in,
                              void* d_out, int out_size) {
    int wi = 4;
    if (n_in >= 4 && in_sizes[3] != 1) wi = 3;
    const float* input   = (const float*)d_in[0];
    const float* onehots = (const float*)d_in[1];
    const float* Wh  = (const float*)d_in[wi + 0];
    const float* bh  = (const float*)d_in[wi + 1];
    const float* Wc  = (const float*)d_in[wi + 2];
    const float* bc  = (const float*)d_in[wi + 3];
    const float* Wih = (const float*)d_in[wi + 4];
    const float* Whh = (const float*)d_in[wi + 5];
    const float* bih = (const float*)d_in[wi + 6];
    const float* bhh = (const float*)d_in[wi + 7];
    const float* W1  = (const float*)d_in[wi + 8];
    const float* b1  = (const float*)d_in[wi + 9];
    const float* W2  = (const float*)d_in[wi + 10];
    const float* b2  = (const float*)d_in[wi + 11];
    float* out = (float*)d_out;
    (void)out_size;

    cudaFuncSetAttribute(step_kernel, cudaFuncAttributeMaxDynamicSharedMemorySize, SMEM_TOT);

    init_kernel<<<B_, 256>>>(input, onehots, Wh, bh, Wc, bc);
    prep_B<<<FH_, 128>>>(Whh, bih, bhh);
    prep_misc<<<V_ + (H_ * G_ + G_ * V_ + 255) / 256, 256>>>(Wih, W1, W2);
    step_kernel<<<dim3(MT_, NT_), 384, SMEM_TOT>>>(b1, b2, out);
}

// round 17
// speedup vs baseline: 1.4658x; 1.4658x over previous
#include <cuda_runtime.h>
#include <cuda_bf16.h>
#include <math.h>
#include <stdint.h>

// Problem constants
#define B_   1024
#define T_   64
#define H_   512
#define V_   1024
#define G_   100
#define FH_  2048   // 4*H

// GEMM tiling: CTA tile 64(M) x 128(N'), BK=32, 8 GEMM warps (32x32 each), 2 CTAs/SM
#define MT_   16
#define NT_   16
#define GRID_ 256
#define BK_   32
#define NK_   16
#define APL_  4096    // A plane bytes: 64 rows * 64B
#define BPL_  8192    // B plane bytes: 128 rows * 64B
#define STAGE_B 36864 // 3*APL + 3*BPL
#define NSTG  2
#define HR    4       // head rows per CTA
#define HEAD_OFF (NSTG * STAGE_B)                               // 73728
#define SMEM_TOT (HEAD_OFF + HR * V_ * 4 + HR * (G_ + 4) * 4)  // 91776 -> 2 CTAs/SM

// ---------------- persistent device scratch ----------------
__device__ float g_h[2][B_ * H_];
__device__ float g_c[B_ * H_];
__device__ int   g_tok[B_];
__device__ float g_bR[FH_];
__device__ float g_WihR[(size_t)V_ * FH_];
__device__ __nv_bfloat16 g_Bs[3][(size_t)FH_ * H_];
__device__ __nv_bfloat16 g_Ab[2][3][B_][H_];
__device__ float g_W1T[H_ * G_];
__device__ float g_W2T[G_ * V_];
__device__ unsigned g_edc[GRID_];  // per-CTA epilogue-done flags (A-chunk producers); idx mt*16+nt
__device__ unsigned g_ed[16];      // per-m-group epilogue-done counters (head waits)
__device__ unsigned g_hd[16];      // per-m-group head-done (tok ready) counters

__device__ __forceinline__ int np_to_gr(int np) {
    int nt = np >> 7, rem = np & 127, jl = rem >> 2, gg = rem & 3;
    return gg * 512 + nt * 32 + jl;
}

__device__ __forceinline__ uint32_t smem_u32(const void* p) {
    uint32_t a;
    asm("{ .reg .u64 t; cvta.to.shared.u64 t, %1; cvt.u32.u64 %0, t; }" : "=r"(a) : "l"(p));
    return a;
}

#define CP16(dst, src) \
    asm volatile("cp.async.cg.shared.global [%0], [%1], 16;" :: "r"(dst), "l"(src) : "memory")
#define CP_WAIT_ALL() asm volatile("cp.async.wait_all;" ::: "memory")

#define LDM_X4(r0, r1, r2, r3, addr) \
    asm volatile("ldmatrix.sync.aligned.m8n8.x4.shared.b16 {%0,%1,%2,%3}, [%4];" \
                 : "=r"(r0), "=r"(r1), "=r"(r2), "=r"(r3) : "r"(addr))

#define MMA16816(d0, d1, d2, d3, a0, a1, a2, a3, b0, b1) \
    asm volatile("mma.sync.aligned.m16n8k16.row.col.f32.bf16.bf16.f32 " \
                 "{%0,%1,%2,%3}, {%4,%5,%6,%7}, {%8,%9}, {%0,%1,%2,%3};" \
                 : "+f"(d0), "+f"(d1), "+f"(d2), "+f"(d3) \
                 : "r"(a0), "r"(a1), "r"(a2), "r"(a3), "r"(b0), "r"(b1))

#define BAR_GEMM() asm volatile("bar.sync 1, 256;" ::: "memory")   // warps 0-7
#define BAR_HEAD() asm volatile("bar.sync 2, 128;" ::: "memory")   // warps 8-11

__device__ __forceinline__ void split3(float v, __nv_bfloat16& s0, __nv_bfloat16& s1, __nv_bfloat16& s2) {
    s0 = __float2bfloat16_rn(v);
    float r1 = v - __bfloat162float(s0);
    s1 = __float2bfloat16_rn(r1);
    float r2 = r1 - __bfloat162float(s1);
    s2 = __float2bfloat16_rn(r2);
}

__device__ __forceinline__ uint32_t pl_off(int r, int q) {
    return (uint32_t)(r * 64 + ((q ^ ((r >> 1) & 3)) << 4));
}

// single-thread fenced poll (proven R13-R15 pattern)
__device__ __forceinline__ void spin_ge(unsigned* cnt, unsigned tgt) {
    while (atomicAdd(cnt, 0u) < tgt) { }
    __threadfence();
}

// ---------------- init: h0/c0 (+bf16x3 planes), tok0, flag reset ----------------
__global__ void init_kernel(const float* __restrict__ inp,
                            const float* __restrict__ onehots,
                            const float* __restrict__ Wh, const float* __restrict__ bh,
                            const float* __restrict__ Wc, const float* __restrict__ bc) {
    int b = blockIdx.x;
    if (b == 0) {
        if (threadIdx.x < GRID_) g_edc[threadIdx.x] = 0u;
        if (threadIdx.x < 16) { g_ed[threadIdx.x] = 0u; g_hd[threadIdx.x] = 0u; }
    }
    float x = inp[b];
    for (int j = threadIdx.x; j < H_; j += blockDim.x) {
        float h0 = x * Wh[j] + bh[j];
        g_h[0][b * H_ + j] = h0;
        g_c[b * H_ + j]    = x * Wc[j] + bc[j];
        __nv_bfloat16 s0, s1, s2;
        split3(h0, s0, s1, s2);
        g_Ab[0][0][b][j] = s0;
        g_Ab[0][1][b][j] = s1;
        g_Ab[0][2][b][j] = s2;
    }
    const float* oh = onehots + (size_t)b * T_ * V_;
    for (int v = threadIdx.x; v < V_; v += blockDim.x)
        if (oh[v] > 0.5f) g_tok[b] = v;
}

// ---------------- prep: Whh -> 3 bf16 planes (reordered) + combined bias ----------------
__global__ void prep_B(const float* __restrict__ Whh,
                       const float* __restrict__ bih, const float* __restrict__ bhh) {
    int np = blockIdx.x;
    int gr = np_to_gr(np);
    if (threadIdx.x == 0) g_bR[np] = bih[gr] + bhh[gr];
    for (int k = threadIdx.x; k < H_; k += blockDim.x) {
        __nv_bfloat16 s0, s1, s2;
        split3(Whh[(size_t)gr * H_ + k], s0, s1, s2);
        size_t o = (size_t)np * H_ + k;
        g_Bs[0][o] = s0; g_Bs[1][o] = s1; g_Bs[2][o] = s2;
    }
}

// ---------------- prep: Wih reorder + head weight transposes ----------------
__global__ void prep_misc(const float* __restrict__ Wih,
                          const float* __restrict__ W1,
                          const float* __restrict__ W2) {
    int bid = blockIdx.x;
    if (bid < V_) {
        for (int np = threadIdx.x; np < FH_; np += blockDim.x) {
            int gr = np_to_gr(np);
            g_WihR[(size_t)bid * FH_ + np] = Wih[(size_t)gr * V_ + bid];
        }
    } else {
        int e = (bid - V_) * 256 + threadIdx.x;
        if (e < H_ * G_) {
            int k = e / G_, gg = e % G_;
            g_W1T[e] = W1[gg * H_ + k];
        } else if (e < H_ * G_ + G_ * V_) {
            int e2 = e - H_ * G_;
            int k = e2 / V_, v = e2 % V_;
            g_W2T[e2] = W2[v * G_ + k];
        }
    }
}

// ---------------- persistent fused kernel ----------------
// Distributed sync with CYCLIC chunk order: CTA (mt,nt) consumes chunks ck=(nt+kc)&15.
//   chunk ck of step t needs g_edc[mt*16+ck] >= t (producer = CTA (mt,ck), epi_{t-1});
//     chunk kc=0 is this CTA's own product -> wait trivially satisfied.
//   head_{t-1} (bid) waits g_ed[bid>>4] >= 16t, then increments g_hd[bid>>4]
//   epi_t (mt,nt) waits g_hd[mt] >= 16t, then increments g_edc[mt*16+nt] and g_ed[mt]
__global__ __launch_bounds__(384, 2) void step_kernel(const float* __restrict__ b1,
                                                      const float* __restrict__ b2,
                                                      float* __restrict__ out) {
    extern __shared__ char smem[];
    const int tid = threadIdx.x, wid = tid >> 5, lane = tid & 31;
    const int mt = blockIdx.x, nt = blockIdx.y;
    const int bid = blockIdx.y * MT_ + blockIdx.x;     // 0..255
    const int row0 = bid * HR;                         // head rows
    const int hgrp = bid >> 4;                         // head's h/tok m-group
    uint32_t smem_base = smem_u32(smem);

    float* hbuf = (float*)(smem + HEAD_OFF);
    float (*sh_lg)[V_]     = (float (*)[V_])hbuf;
    float (*sh_h)[H_]      = (float (*)[H_])hbuf;      // alias: phase1 only
    float (*sh_r)[G_ + 4]  = (float (*)[G_ + 4])(hbuf + HR * V_);

    // GEMM-side lane constants (warps 0-7): 2x4 warp grid, warp tile 32m x 32n
    const int gq = lane >> 2, tq = lane & 3;
    const int mwarp = (wid >> 2) * 32;
    const int nwarp = (wid & 3) * 32;
    const int t8 = lane >> 3, lr = lane & 7;
    const int thi = t8 >> 1, tlo = t8 & 1;
    uint32_t aBase[2], aX[2];
    #pragma unroll
    for (int mi = 0; mi < 2; mi++) {
        int r = mwarp + mi * 16 + (tlo << 3) + lr;
        aBase[mi] = (uint32_t)(r * 64);
        aX[mi] = (uint32_t)(((r >> 1) & 3) << 4);
    }
    uint32_t bBase[2], bX[2];
    #pragma unroll
    for (int nih = 0; nih < 2; nih++) {
        int n = nwarp + nih * 16 + (thi << 3) + lr;
        bBase[nih] = (uint32_t)(n * 64);
        bX[nih] = (uint32_t)(((n >> 1) & 3) << 4);
    }
    const int ht = tid - 256;                          // head thread id (warps 8-11)

    // B half of a chunk (step-invariant)
    #define LOAD_B(ck, st) do { \
        uint32_t bb = smem_base + (st) * STAGE_B + 3 * APL_; \
        _Pragma("unroll") \
        for (int s = 0; s < 6; s++) { \
            int e = tid + 256 * s; \
            int p = e >> 9, rem = e & 511, n = rem >> 2, q = rem & 3; \
            CP16(bb + p * BPL_ + pl_off(n, q), \
                 &g_Bs[p][(size_t)(nt * 128 + n) * H_ + (ck) * BK_ + q * 8]); \
        } \
    } while (0)

    // A half of a chunk (after the chunk's producer flag)
    #define LOAD_A(ck, st, par) do { \
        uint32_t bb = smem_base + (st) * STAGE_B; \
        _Pragma("unroll") \
        for (int s = 0; s < 3; s++) { \
            int e = tid + 256 * s; \
            int p = e >> 8, rem = e & 255, n = rem >> 2, q = rem & 3; \
            CP16(bb + p * APL_ + pl_off(n, q), \
                 &g_Ab[par][p][mt * 64 + n][(ck) * BK_ + q * 8]); \
        } \
    } while (0)

    for (int t = 0; t <= T_; t++) {
        int par = t & 1;
        float acc[2][4][4];

        if (wid < 8) {
            if (t < T_) {
                // =========== gates GEMM for step t (cyclic chunk order) ===========
                #pragma unroll
                for (int mi = 0; mi < 2; mi++)
                    #pragma unroll
                    for (int n8 = 0; n8 < 4; n8++)
                        #pragma unroll
                        for (int q = 0; q < 4; q++) acc[mi][n8][q] = 0.0f;

                int ck0 = nt;                      // own chunk first
                LOAD_B(ck0, 0);
                if (tid == 0 && t > 0) spin_ge(&g_edc[mt * 16 + ck0], (unsigned)t);
                BAR_GEMM();
                LOAD_A(ck0, 0, par);
                CP_WAIT_ALL();
                BAR_GEMM();

                for (int kc = 0; kc < NK_; kc++) {
                    int cur = kc & 1, nxt = cur ^ 1;
                    if (kc + 1 < NK_) {
                        int ckn = (nt + kc + 1) & 15;
                        LOAD_B(ckn, nxt);
                        if (tid == 0 && t > 0) spin_ge(&g_edc[mt * 16 + ckn], (unsigned)t);
                        BAR_GEMM();
                        LOAD_A(ckn, nxt, par);
                    }
                    uint32_t sbase = smem_base + cur * STAGE_B;
                    #pragma unroll
                    for (int kk = 0; kk < 2; kk++) {
                        uint32_t aCh = (uint32_t)((kk * 2 + thi) << 4);
                        uint32_t bCh = (uint32_t)((kk * 2 + tlo) << 4);
                        uint32_t afr[3][2][4];
                        #pragma unroll
                        for (int pa = 0; pa < 3; pa++)
                            #pragma unroll
                            for (int mi = 0; mi < 2; mi++)
                                LDM_X4(afr[pa][mi][0], afr[pa][mi][1], afr[pa][mi][2], afr[pa][mi][3],
                                       sbase + pa * APL_ + aBase[mi] + (aCh ^ aX[mi]));
                        #pragma unroll
                        for (int pb = 0; pb < 3; pb++) {
                            uint32_t bfr[2][4];
                            #pragma unroll
                            for (int nih = 0; nih < 2; nih++)
                                LDM_X4(bfr[nih][0], bfr[nih][1], bfr[nih][2], bfr[nih][3],
                                       sbase + 3 * APL_ + pb * BPL_ + bBase[nih] + (bCh ^ bX[nih]));
                            #pragma unroll
                            for (int pa = 0; pa < 3; pa++) {
                                if (pa + pb > 2) break;
                                #pragma unroll
                                for (int mi = 0; mi < 2; mi++)
                                    #pragma unroll
                                    for (int n8 = 0; n8 < 4; n8++)
                                        MMA16816(acc[mi][n8][0], acc[mi][n8][1], acc[mi][n8][2], acc[mi][n8][3],
                                                 afr[pa][mi][0], afr[pa][mi][1], afr[pa][mi][2], afr[pa][mi][3],
                                                 bfr[n8 >> 1][(n8 & 1) * 2], bfr[n8 >> 1][(n8 & 1) * 2 + 1]);
                            }
                        }
                    }
                    CP_WAIT_ALL();
                    BAR_GEMM();
                }

                // =========== epilogue: wait tok_{t-1}, LSTM update, publish ===========
                if (tid == 0 && t > 0) spin_ge(&g_hd[mt], 16u * (unsigned)t);
                BAR_GEMM();

                float* __restrict__ hout = g_h[par ^ 1];
                #pragma unroll
                for (int mi = 0; mi < 2; mi++) {
                    int r0 = mwarp + mi * 16 + gq;
                    int m0 = mt * 64 + r0;
                    int m1 = m0 + 8;
                    int tok0 = __ldcg(&g_tok[m0]);
                    int tok1 = __ldcg(&g_tok[m1]);
                    const float* w0 = g_WihR + (size_t)tok0 * FH_;
                    const float* w1 = g_WihR + (size_t)tok1 * FH_;
                    #pragma unroll
                    for (int n8 = 0; n8 < 4; n8++) {
                        float c0 = acc[mi][n8][0], c1 = acc[mi][n8][1];
                        float c2 = acc[mi][n8][2], c3 = acc[mi][n8][3];
                        float gv0 = __shfl_xor_sync(0xffffffffu, c0, 1);
                        float ov0 = __shfl_xor_sync(0xffffffffu, c1, 1);
                        float gv1 = __shfl_xor_sync(0xffffffffu, c2, 1);
                        float ov1 = __shfl_xor_sync(0xffffffffu, c3, 1);
                        if (!(lane & 1)) {
                            int colq = nt * 128 + nwarp + n8 * 8 + 2 * tq;
                            float4 b4 = *(const float4*)&g_bR[colq];
                            float4 wa = *(const float4*)&w0[colq];
                            float4 wb = *(const float4*)&w1[colq];
                            int j = colq >> 2;
                            {
                                float gi = c0 + wa.x + b4.x;
                                float gf = c1 + wa.y + b4.y;
                                float gg = gv0 + wa.z + b4.z;
                                float go = ov0 + wa.w + b4.w;
                                float si = 1.0f / (1.0f + expf(-gi));
                                float sf = 1.0f / (1.0f + expf(-gf));
                                float so = 1.0f / (1.0f + expf(-go));
                                size_t idx = (size_t)m0 * H_ + j;
                                float cn = sf * g_c[idx] + si * tanhf(gg);
                                float hn = so * tanhf(cn);
                                g_c[idx] = cn;
                                hout[idx] = hn;
                                __nv_bfloat16 s0, s1, s2;
                                split3(hn, s0, s1, s2);
                                g_Ab[par ^ 1][0][m0][j] = s0;
                                g_Ab[par ^ 1][1][m0][j] = s1;
                                g_Ab[par ^ 1][2][m0][j] = s2;
                            }
                            {
                                float gi = c2 + wb.x + b4.x;
                                float gf = c3 + wb.y + b4.y;
                                float gg = gv1 + wb.z + b4.z;
                                float go = ov1 + wb.w + b4.w;
                                float si = 1.0f / (1.0f + expf(-gi));
                                float sf = 1.0f / (1.0f + expf(-gf));
                                float so = 1.0f / (1.0f + expf(-go));
                                size_t idx = (size_t)m1 * H_ + j;
                                float cn = sf * g_c[idx] + si * tanhf(gg);
                                float hn = so * tanhf(cn);
                                g_c[idx] = cn;
                                hout[idx] = hn;
                                __nv_bfloat16 s0, s1, s2;
                                split3(hn, s0, s1, s2);
                                g_Ab[par ^ 1][0][m1][j] = s0;
                                g_Ab[par ^ 1][1][m1][j] = s1;
                                g_Ab[par ^ 1][2][m1][j] = s2;
                            }
                        }
                    }
                }
                BAR_GEMM();
                if (tid == 0) {
                    __threadfence();
                    atomicAdd(&g_edc[mt * 16 + nt], 1u);
                    atomicAdd(&g_ed[mt], 1u);
                }
            }
        } else {
            // =========== head for step t-1 (concurrent with GEMM_t) ===========
            if (t >= 1) {
                if (ht == 0) spin_ge(&g_ed[hgrp], 16u * (unsigned)t);
                BAR_HEAD();

                const float* __restrict__ h = g_h[par];   // written by epi_{t-1}
                for (int e = ht; e < HR * H_ / 4; e += 128) {
                    int rr = e >> 7, q = e & 127;
                    float4 v = __ldcg((const float4*)&h[(size_t)(row0 + rr) * H_ + q * 4]);
                    *(float4*)&sh_h[rr][q * 4] = v;
                }
                BAR_HEAD();
                if (ht < G_) {
                    float a4[HR] = {0.f, 0.f, 0.f, 0.f};
                    for (int k = 0; k < H_; k++) {
                        float w = g_W1T[k * G_ + ht];
                        #pragma unroll
                        for (int r2 = 0; r2 < HR; r2++) a4[r2] += w * sh_h[r2][k];
                    }
                    float bb = b1[ht];
                    #pragma unroll
                    for (int r2 = 0; r2 < HR; r2++) sh_r[r2][ht] = fmaxf(a4[r2] + bb, 0.0f);
                }
                BAR_HEAD();
                #pragma unroll
                for (int s = 0; s < 8; s++) {
                    int v = ht + 128 * s;
                    float a4[HR];
                    #pragma unroll
                    for (int rr = 0; rr < HR; rr++) a4[rr] = 0.0f;
                    for (int k = 0; k < G_; k++) {
                        float w = g_W2T[k * V_ + v];
                        #pragma unroll
                        for (int rr = 0; rr < HR; rr++) a4[rr] += w * sh_r[rr][k];
                    }
                    float bb = b2[v];
                    #pragma unroll
                    for (int rr = 0; rr < HR; rr++) sh_lg[rr][v] = a4[rr] + bb;
                }
                BAR_HEAD();
                // softmax/argmax: 1 warp per row
                {
                    int rr = wid - 8;
                    float x[32];
                    #pragma unroll
                    for (int q = 0; q < 8; q++) {
                        float4 v4 = *(const float4*)&sh_lg[rr][q * 128 + lane * 4];
                        x[q * 4 + 0] = v4.x; x[q * 4 + 1] = v4.y; x[q * 4 + 2] = v4.z; x[q * 4 + 3] = v4.w;
                    }
                    float m = x[0];
                    int mi = lane * 4;
                    #pragma unroll
                    for (int q = 0; q < 8; q++)
                        #pragma unroll
                        for (int e = 0; e < 4; e++) {
                            if (q == 0 && e == 0) continue;
                            int col = q * 128 + lane * 4 + e;
                            float v = x[q * 4 + e];
                            if (v > m || (v == m && col < mi)) { m = v; mi = col; }
                        }
                    #pragma unroll
                    for (int o = 16; o > 0; o >>= 1) {
                        float om = __shfl_down_sync(0xffffffffu, m, o);
                        int oi = __shfl_down_sync(0xffffffffu, mi, o);
                        if (om > m || (om == m && oi < mi)) { m = om; mi = oi; }
                    }
                    float fm = __shfl_sync(0xffffffffu, m, 0);
                    int fi = __shfl_sync(0xffffffffu, mi, 0);
                    if (lane == 0) g_tok[row0 + rr] = fi;

                    float sum = 0.0f;
                    #pragma unroll
                    for (int e = 0; e < 32; e++) sum += __expf(x[e] - fm);
                    #pragma unroll
                    for (int o = 16; o > 0; o >>= 1) sum += __shfl_xor_sync(0xffffffffu, sum, o);
                    float lse = fm + __logf(sum);

                    float* orow = out + (size_t)(t - 1) * B_ * V_ + (size_t)(row0 + rr) * V_;
                    #pragma unroll
                    for (int q = 0; q < 8; q++) {
                        float4 ov = make_float4(x[q * 4 + 0] - lse, x[q * 4 + 1] - lse,
                                                x[q * 4 + 2] - lse, x[q * 4 + 3] - lse);
                        *(float4*)&orow[q * 128 + lane * 4] = ov;
                    }
                }
                BAR_HEAD();
                if (ht == 0) { __threadfence(); atomicAdd(&g_hd[hgrp], 1u); }
            }
        }
    }
    #undef LOAD_B
    #undef LOAD_A
}

// ---------------- launch ----------------
extern "C" void kernel_launch(void* const* d_in, const int* in_sizes, int n_in,
                              void* d_out, int out_size) {
    int wi = 4;
    if (n_in >= 4 && in_sizes[3] != 1) wi = 3;
    const float* input   = (const float*)d_in[0];
    const float* onehots = (const float*)d_in[1];
    const float* Wh  = (const float*)d_in[wi + 0];
    const float* bh  = (const float*)d_in[wi + 1];
    const float* Wc  = (const float*)d_in[wi + 2];
    const float* bc  = (const float*)d_in[wi + 3];
    const float* Wih = (const float*)d_in[wi + 4];
    const float* Whh = (const float*)d_in[wi + 5];
    const float* bih = (const float*)d_in[wi + 6];
    const float* bhh = (const float*)d_in[wi + 7];
    const float* W1  = (const float*)d_in[wi + 8];
    const float* b1  = (const float*)d_in[wi + 9];
    const float* W2  = (const float*)d_in[wi + 10];
    const float* b2  = (const float*)d_in[wi + 11];
    float* out = (float*)d_out;
    (void)out_size;

    cudaFuncSetAttribute(step_kernel, cudaFuncAttributeMaxDynamicSharedMemorySize, SMEM_TOT);

    init_kernel<<<B_, 256>>>(input, onehots, Wh, bh, Wc, bc);
    prep_B<<<FH_, 128>>>(Whh, bih, bhh);
    prep_misc<<<V_ + (H_ * G_ + G_ * V_ + 255) / 256, 256>>>(Wih, W1, W2);
    step_kernel<<<dim3(MT_, NT_), 384, SMEM_TOT>>>(b1, b2, out);
}